// round 9
// baseline (speedup 1.0000x reference)
#include <cuda_runtime.h>
#include <cuda_bf16.h>

#define HW 4096
#define NM 512

__device__ float  g_c[64], g_s[64];
__device__ __nv_bfloat162 g_wmixB[6 * NM * 4096]; // [j][m][o][i], scaled c_ky/4096
__device__ float2 g_specX[NM * 2048];             // [m][bt*64+c]
__device__ float2 g_specB[3 * NM * 2048];         // [jj][m][bt*64+o]
__device__ float2 g_specH[NM * 256];              // spectrum of current h
__device__ float2 g_specRH[NM * 256];             // spectrum of rh
__device__ float  g_Ax[3 * 32 * 64 * HW];         // [jj][bt][o][p]
__device__ float  g_S13[2 * 4 * 64 * HW];
__device__ float  g_S5[4 * 64 * HW];
__device__ float  g_z[4 * 64 * HW];
__device__ float  g_rh[4 * 64 * HW];
__device__ float  g_h[4 * 64 * HW];

__global__ void k_twiddle() {
    int n = threadIdx.x;
    float s, c;
    sincospif(n * (1.0f / 32.0f), &s, &c);
    g_c[n] = c; g_s[n] = s;
}

// sw[j][i][o][kx][ky][2] -> g_wmixB[j][m][o][i] bf16x2, scale c_ky/4096
__global__ __launch_bounds__(256) void k_wtransB(const float* __restrict__ sw1,
                                                 const float* __restrict__ sw2) {
    int it = blockIdx.x, o = blockIdx.y, j = blockIdx.z, tid = threadIdx.x;
    __shared__ float t1[8 * 512], t2[8 * 512];
    for (int idx = tid; idx < 8 * 512; idx += 256) {
        int ii = idx >> 9, q = idx & 511;
        size_t src = ((size_t)((j * 64 + it * 8 + ii) * 64) + o) * 512 + q;
        t1[idx] = sw1[src];
        t2[idx] = sw2[src];
    }
    __syncthreads();
    for (int idx = tid; idx < 512 * 8; idx += 256) {
        int m = idx >> 3, ii = idx & 7;
        int kxi = m >> 4, ky = m & 15;
        float f = (ky == 0 ? 1.f : 2.f) * (1.f / 4096.f);
        const float* tt = (kxi < 16) ? t1 : t2;
        int kk = (kxi < 16) ? kxi : kxi - 16;
        float re = tt[ii * 512 + kk * 32 + ky * 2] * f;
        float im = tt[ii * 512 + kk * 32 + ky * 2 + 1] * f;
        g_wmixB[((size_t)(j * 512 + m) * 64 + o) * 64 + it * 8 + ii] =
            __floats2bfloat162_rn(re, im);
    }
}

__global__ void k_hinit(const float* __restrict__ bh) {
    float v = bh[0];
    int idx = blockIdx.x * 256 + threadIdx.x;
    g_h[idx] = v;
}

// partial forward DFT of one 64x64 image -> spec[m][img], m=kxi*16+ky
__global__ __launch_bounds__(256) void k_fwd(const float* __restrict__ in,
                                             float2* __restrict__ spec, int nimg) {
    __shared__ float xs[64 * 65];
    __shared__ float Yre[64 * 17], Yim[64 * 17];
    __shared__ float cs[64], ss[64];
    int tid = threadIdx.x, img = blockIdx.x;
    if (tid < 64) { cs[tid] = g_c[tid]; ss[tid] = g_s[tid]; }
    const float* src = in + (size_t)img * HW;
    for (int idx = tid; idx < HW; idx += 256)
        xs[(idx >> 6) * 65 + (idx & 63)] = src[idx];
    __syncthreads();
    {
        int x = tid >> 2, kq = tid & 3;
        const float* row = xs + x * 65;
        float ar[4] = {0,0,0,0}, ai[4] = {0,0,0,0};
        int ii[4] = {0,0,0,0};
        #pragma unroll 8
        for (int y = 0; y < 64; y++) {
            float v = row[y];
            #pragma unroll
            for (int k = 0; k < 4; k++) {
                ar[k] += v * cs[ii[k]];
                ai[k] -= v * ss[ii[k]];
                ii[k] = (ii[k] + kq * 4 + k) & 63;
            }
        }
        #pragma unroll
        for (int k = 0; k < 4; k++) { Yre[x*17 + kq*4+k] = ar[k]; Yim[x*17 + kq*4+k] = ai[k]; }
    }
    __syncthreads();
    {
        int ky = tid & 15, kg = tid >> 4;
        float z0r=0, z0i=0, z1r=0, z1i=0;
        int i0 = 0, i1 = 0;
        #pragma unroll 8
        for (int x = 0; x < 64; x++) {
            float yr = Yre[x*17 + ky], yi = Yim[x*17 + ky];
            float c = cs[i0], s = ss[i0];
            z0r += yr*c + yi*s; z0i += yi*c - yr*s;
            c = cs[i1]; s = ss[i1];
            z1r += yr*c + yi*s; z1i += yi*c - yr*s;
            i0 = (i0 + kg) & 63; i1 = (i1 + kg + 48) & 63;
        }
        spec[(size_t)(kg * 16 + ky) * nimg + img]        = make_float2(z0r, z0i);
        spec[(size_t)((kg + 16) * 16 + ky) * nimg + img] = make_float2(z1r, z1i);
    }
}

// mode mix, 32-image precompute (bf16 weights, padded smem transpose)
__global__ __launch_bounds__(256) void k_mix32() {
    int m = blockIdx.x, jj = blockIdx.y, tid = threadIdx.x;
    const __nv_bfloat162* W = g_wmixB + (size_t)((2 * jj) * 512 + m) * 4096;
    __shared__ float wr[64 * 65], wi[64 * 65];   // [i][o] padded
    __shared__ float2 ins[1024];
    for (int idx = tid; idx < 4096; idx += 256) {
        int o = idx >> 6, i = idx & 63;
        float2 w = __bfloat1622float2(W[idx]);
        wr[i * 65 + o] = w.x;
        wi[i * 65 + o] = w.y;
    }
    int o = tid & 63, bq = tid >> 6;
    for (int hh = 0; hh < 2; hh++) {
        __syncthreads();
        for (int idx = tid; idx < 1024; idx += 256)
            ins[idx] = g_specX[(size_t)m * 2048 + hh * 1024 + idx];
        __syncthreads();
        float2 acc[4];
        #pragma unroll
        for (int g = 0; g < 4; g++) acc[g] = make_float2(0.f, 0.f);
        for (int i = 0; i < 64; i++) {
            float wrv = wr[i * 65 + o], wiv = wi[i * 65 + o];
            #pragma unroll
            for (int g = 0; g < 4; g++) {
                float2 iv = ins[(g * 4 + bq) * 64 + i];
                acc[g].x += iv.x * wrv - iv.y * wiv;
                acc[g].y += iv.x * wiv + iv.y * wrv;
            }
        }
        float2* outp = g_specB + (size_t)jj * NM * 2048 + (size_t)m * 2048 + hh * 1024;
        #pragma unroll
        for (int g = 0; g < 4; g++) outp[(g * 4 + bq) * 64 + o] = acc[g];
    }
}

// precompute inverse: g_Ax[jj] += irfft(specB[jj])
__global__ __launch_bounds__(256) void k_invPre() {
    int img = blockIdx.x, jj = blockIdx.y, tid = threadIdx.x;
    const float2* spec = g_specB + (size_t)jj * NM * 2048;
    __shared__ float Zr[512], Zi[512];
    __shared__ __align__(16) float Gr[16 * 68];
    __shared__ __align__(16) float Gi[16 * 68];
    __shared__ float cs[64], ss[64];
    if (tid < 64) { cs[tid] = g_c[tid]; ss[tid] = g_s[tid]; }
    for (int idx = tid; idx < 512; idx += 256) {
        float2 v = spec[(size_t)idx * 2048 + img];
        Zr[idx] = v.x; Zi[idx] = v.y;
    }
    __syncthreads();
    {
        int ky = tid & 15, xg = tid >> 4, x0 = xg * 4;
        float gr[4] = {0,0,0,0}, gi[4] = {0,0,0,0};
        #pragma unroll 4
        for (int kxi = 0; kxi < 32; kxi++) {
            int kx = kxi + ((kxi >= 16) ? 32 : 0);
            float zr = Zr[kxi * 16 + ky], zi = Zi[kxi * 16 + ky];
            #pragma unroll
            for (int k = 0; k < 4; k++) {
                int id = (kx * (x0 + k)) & 63;
                float c = cs[id], s = ss[id];
                gr[k] += zr * c - zi * s;
                gi[k] += zr * s + zi * c;
            }
        }
        #pragma unroll
        for (int k = 0; k < 4; k++) { Gr[ky*68 + x0+k] = gr[k]; Gi[ky*68 + x0+k] = gi[k]; }
    }
    __syncthreads();
    {
        int y = tid & 63, xq = tid >> 6;
        float acc[16];
        #pragma unroll
        for (int q = 0; q < 16; q++) acc[q] = 0.f;
        for (int ky = 0; ky < 16; ky++) {
            int id = (ky * y) & 63;
            float c = cs[id], s = ss[id];
            const float4* a4 = (const float4*)(Gr + ky * 68 + xq * 16);
            const float4* b4 = (const float4*)(Gi + ky * 68 + xq * 16);
            #pragma unroll
            for (int q = 0; q < 4; q++) {
                float4 a = a4[q], b = b4[q];
                acc[q*4+0] += a.x * c - b.x * s;
                acc[q*4+1] += a.y * c - b.y * s;
                acc[q*4+2] += a.z * c - b.z * s;
                acc[q*4+3] += a.w * c - b.w * s;
            }
        }
        float* outp = g_Ax + (size_t)jj * 32 * 64 * HW + (size_t)img * HW;
        #pragma unroll
        for (int q = 0; q < 16; q++) {
            int off = (xq * 16 + q) * 64 + y;
            outp[off] += acc[q];
        }
    }
}

// Ax[jj][bt][o][p] = sum_i x[bt][i][p] * skw[2jj][i][o]
__global__ __launch_bounds__(256) void k_skipx(const float* __restrict__ x,
                                               const float* __restrict__ skw) {
    int p0 = blockIdx.x * 64, bt = blockIdx.y, jj = blockIdx.z, tid = threadIdx.x;
    __shared__ __align__(16) float xs[4096];
    __shared__ __align__(16) float ws[4096];
    {
        float4* xs4 = (float4*)xs;
        float4* ws4 = (float4*)ws;
        const float4* wsrc = (const float4*)(skw + (size_t)(2 * jj) * 4096);
        for (int idx = tid; idx < 1024; idx += 256) {
            int c = idx >> 4, v = idx & 15;
            xs4[idx] = *(const float4*)(x + (size_t)(bt * 64 + c) * HW + p0 + v * 4);
            ws4[idx] = wsrc[idx];
        }
    }
    __syncthreads();
    int pi = (tid & 15) * 4, o0 = (tid >> 4) * 4;
    float4 a[4];
    #pragma unroll
    for (int k = 0; k < 4; k++) a[k] = make_float4(0.f, 0.f, 0.f, 0.f);
    #pragma unroll 4
    for (int i = 0; i < 64; i++) {
        float4 xv = *(const float4*)(xs + i * 64 + pi);
        float4 wv = *(const float4*)(ws + i * 64 + o0);
        a[0].x += wv.x*xv.x; a[0].y += wv.x*xv.y; a[0].z += wv.x*xv.z; a[0].w += wv.x*xv.w;
        a[1].x += wv.y*xv.x; a[1].y += wv.y*xv.y; a[1].z += wv.y*xv.z; a[1].w += wv.y*xv.w;
        a[2].x += wv.z*xv.x; a[2].y += wv.z*xv.y; a[2].z += wv.z*xv.z; a[2].w += wv.z*xv.w;
        a[3].x += wv.w*xv.x; a[3].y += wv.w*xv.y; a[3].z += wv.w*xv.z; a[3].w += wv.w*xv.w;
    }
    #pragma unroll
    for (int oi = 0; oi < 4; oi++)
        *(float4*)(g_Ax + ((size_t)(jj * 32 + bt) * 64 + o0 + oi) * HW + p0 + pi) = a[oi];
}

// S13[w][b][o][p] = sum_i h[b][i][p] * skw[1 or 3][i][o]
__global__ __launch_bounds__(256) void k_hskip13(const float* __restrict__ skw) {
    int p0 = blockIdx.x * 64, b = blockIdx.y, tid = threadIdx.x;
    __shared__ __align__(16) float hs[4096];
    __shared__ __align__(16) float w1s[4096];
    __shared__ __align__(16) float w3s[4096];
    {
        float4* h4 = (float4*)hs;
        float4* a4 = (float4*)w1s;
        float4* b4 = (float4*)w3s;
        const float4* w1src = (const float4*)(skw + 4096);
        const float4* w3src = (const float4*)(skw + 3 * 4096);
        for (int idx = tid; idx < 1024; idx += 256) {
            int c = idx >> 4, v = idx & 15;
            h4[idx] = *(const float4*)(g_h + (size_t)(b * 64 + c) * HW + p0 + v * 4);
            a4[idx] = w1src[idx];
            b4[idx] = w3src[idx];
        }
    }
    __syncthreads();
    int pi = (tid & 15) * 4, o0 = (tid >> 4) * 4;
    float4 a1[4], a3[4];
    #pragma unroll
    for (int k = 0; k < 4; k++) { a1[k] = make_float4(0,0,0,0); a3[k] = make_float4(0,0,0,0); }
    #pragma unroll 2
    for (int i = 0; i < 64; i++) {
        float4 xv = *(const float4*)(hs + i * 64 + pi);
        float4 wa = *(const float4*)(w1s + i * 64 + o0);
        float4 wb = *(const float4*)(w3s + i * 64 + o0);
        a1[0].x += wa.x*xv.x; a1[0].y += wa.x*xv.y; a1[0].z += wa.x*xv.z; a1[0].w += wa.x*xv.w;
        a1[1].x += wa.y*xv.x; a1[1].y += wa.y*xv.y; a1[1].z += wa.y*xv.z; a1[1].w += wa.y*xv.w;
        a1[2].x += wa.z*xv.x; a1[2].y += wa.z*xv.y; a1[2].z += wa.z*xv.z; a1[2].w += wa.z*xv.w;
        a1[3].x += wa.w*xv.x; a1[3].y += wa.w*xv.y; a1[3].z += wa.w*xv.z; a1[3].w += wa.w*xv.w;
        a3[0].x += wb.x*xv.x; a3[0].y += wb.x*xv.y; a3[0].z += wb.x*xv.z; a3[0].w += wb.x*xv.w;
        a3[1].x += wb.y*xv.x; a3[1].y += wb.y*xv.y; a3[1].z += wb.y*xv.z; a3[1].w += wb.y*xv.w;
        a3[2].x += wb.z*xv.x; a3[2].y += wb.z*xv.y; a3[2].z += wb.z*xv.z; a3[2].w += wb.z*xv.w;
        a3[3].x += wb.w*xv.x; a3[3].y += wb.w*xv.y; a3[3].z += wb.w*xv.z; a3[3].w += wb.w*xv.w;
    }
    #pragma unroll
    for (int oi = 0; oi < 4; oi++) {
        *(float4*)(g_S13 + ((size_t)(0 * 4 + b) * 64 + o0 + oi) * HW + p0 + pi) = a1[oi];
        *(float4*)(g_S13 + ((size_t)(1 * 4 + b) * 64 + o0 + oi) * HW + p0 + pi) = a3[oi];
    }
}

// S5[b][o][p] = sum_i rh[b][i][p] * skw[5][i][o]
__global__ __launch_bounds__(256) void k_skip5(const float* __restrict__ skw) {
    int p0 = blockIdx.x * 64, b = blockIdx.y, tid = threadIdx.x;
    __shared__ __align__(16) float rs[4096];
    __shared__ __align__(16) float ws[4096];
    {
        float4* r4 = (float4*)rs;
        float4* w4 = (float4*)ws;
        const float4* wsrc = (const float4*)(skw + 5 * 4096);
        for (int idx = tid; idx < 1024; idx += 256) {
            int c = idx >> 4, v = idx & 15;
            r4[idx] = *(const float4*)(g_rh + (size_t)(b * 64 + c) * HW + p0 + v * 4);
            w4[idx] = wsrc[idx];
        }
    }
    __syncthreads();
    int pi = (tid & 15) * 4, o0 = (tid >> 4) * 4;
    float4 a[4];
    #pragma unroll
    for (int k = 0; k < 4; k++) a[k] = make_float4(0.f, 0.f, 0.f, 0.f);
    #pragma unroll 4
    for (int i = 0; i < 64; i++) {
        float4 xv = *(const float4*)(rs + i * 64 + pi);
        float4 wv = *(const float4*)(ws + i * 64 + o0);
        a[0].x += wv.x*xv.x; a[0].y += wv.x*xv.y; a[0].z += wv.x*xv.z; a[0].w += wv.x*xv.w;
        a[1].x += wv.y*xv.x; a[1].y += wv.y*xv.y; a[1].z += wv.y*xv.z; a[1].w += wv.y*xv.w;
        a[2].x += wv.z*xv.x; a[2].y += wv.z*xv.y; a[2].z += wv.z*xv.z; a[2].w += wv.z*xv.w;
        a[3].x += wv.w*xv.x; a[3].y += wv.w*xv.y; a[3].z += wv.w*xv.z; a[3].w += wv.w*xv.w;
    }
    #pragma unroll
    for (int oi = 0; oi < 4; oi++)
        *(float4*)(g_S5 + ((size_t)b * 64 + o0 + oi) * HW + p0 + pi) = a[oi];
}

// fused: mode-mix (w1,w3) of specH + inverse DFT + gates + forward DFT of rh
__global__ __launch_bounds__(256) void k_invmixZR(const float* __restrict__ gb, int t) {
    int img = blockIdx.x, tid = threadIdx.x;
    int b = img >> 6, o = img & 63;
    __shared__ float Zr[2][512], Zi[2][512];
    __shared__ __align__(16) float Gr[2][16 * 68];
    __shared__ __align__(16) float Gi[2][16 * 68];
    __shared__ float xs[64 * 65];
    __shared__ float cs[64], ss[64];
    if (tid < 64) { cs[tid] = g_c[tid]; ss[tid] = g_s[tid]; }
    // mix: each thread computes 2 modes for both weights
    #pragma unroll
    for (int mm = 0; mm < 2; mm++) {
        int m = tid + mm * 256;
        const float2* ih = g_specH + (size_t)m * 256 + b * 64;
        const __nv_bfloat162* w1 = g_wmixB + ((size_t)(1 * 512 + m) * 64 + o) * 64;
        const __nv_bfloat162* w3 = g_wmixB + ((size_t)(3 * 512 + m) * 64 + o) * 64;
        float a0r = 0, a0i = 0, a1r = 0, a1i = 0;
        #pragma unroll 8
        for (int i = 0; i < 64; i++) {
            float2 v = ih[i];
            float2 wa = __bfloat1622float2(w1[i]);
            float2 wb = __bfloat1622float2(w3[i]);
            a0r += v.x * wa.x - v.y * wa.y;
            a0i += v.x * wa.y + v.y * wa.x;
            a1r += v.x * wb.x - v.y * wb.y;
            a1i += v.x * wb.y + v.y * wb.x;
        }
        Zr[0][m] = a0r; Zi[0][m] = a0i;
        Zr[1][m] = a1r; Zi[1][m] = a1i;
    }
    __syncthreads();
    {
        int ky = tid & 15, xg = tid >> 4, x0 = xg * 4;
        #pragma unroll
        for (int jj = 0; jj < 2; jj++) {
            float gr[4] = {0,0,0,0}, gi[4] = {0,0,0,0};
            #pragma unroll 4
            for (int kxi = 0; kxi < 32; kxi++) {
                int kx = kxi + ((kxi >= 16) ? 32 : 0);
                float zr = Zr[jj][kxi * 16 + ky], zi = Zi[jj][kxi * 16 + ky];
                #pragma unroll
                for (int k = 0; k < 4; k++) {
                    int id = (kx * (x0 + k)) & 63;
                    float c = cs[id], s = ss[id];
                    gr[k] += zr * c - zi * s;
                    gi[k] += zr * s + zi * c;
                }
            }
            #pragma unroll
            for (int k = 0; k < 4; k++) { Gr[jj][ky*68 + x0+k] = gr[k]; Gi[jj][ky*68 + x0+k] = gi[k]; }
        }
    }
    __syncthreads();
    {
        int y = tid & 63, xq = tid >> 6;
        float a0[16], a1[16];
        #pragma unroll
        for (int q = 0; q < 16; q++) { a0[q] = 0.f; a1[q] = 0.f; }
        for (int ky = 0; ky < 16; ky++) {
            int id = (ky * y) & 63;
            float c = cs[id], s = ss[id];
            const float4* ar4 = (const float4*)(Gr[0] + ky * 68 + xq * 16);
            const float4* ai4 = (const float4*)(Gi[0] + ky * 68 + xq * 16);
            const float4* br4 = (const float4*)(Gr[1] + ky * 68 + xq * 16);
            const float4* bi4 = (const float4*)(Gi[1] + ky * 68 + xq * 16);
            #pragma unroll
            for (int q = 0; q < 4; q++) {
                float4 xr = ar4[q], xi = ai4[q];
                a0[q*4+0] += xr.x * c - xi.x * s;
                a0[q*4+1] += xr.y * c - xi.y * s;
                a0[q*4+2] += xr.z * c - xi.z * s;
                a0[q*4+3] += xr.w * c - xi.w * s;
                float4 yr = br4[q], yi = bi4[q];
                a1[q*4+0] += yr.x * c - yi.x * s;
                a1[q*4+1] += yr.y * c - yi.y * s;
                a1[q*4+2] += yr.z * c - yi.z * s;
                a1[q*4+3] += yr.w * c - yi.w * s;
            }
        }
        float gb0 = gb[0], gb1 = gb[1];
        int bt = b * 8 + t;
        const float* ax0 = g_Ax + ((size_t)(0 * 32 + bt) * 64 + o) * HW;
        const float* ax1 = g_Ax + ((size_t)(1 * 32 + bt) * 64 + o) * HW;
        const float* s1p = g_S13 + ((size_t)(0 * 4 + b) * 64 + o) * HW;
        const float* s3p = g_S13 + ((size_t)(1 * 4 + b) * 64 + o) * HW;
        const float* hp  = g_h + (size_t)img * HW;
        float* zp  = g_z + (size_t)img * HW;
        float* rhp = g_rh + (size_t)img * HW;
        #pragma unroll
        for (int q = 0; q < 16; q++) {
            int x = xq * 16 + q;
            int off = x * 64 + y;
            float pre0 = a0[q] + ax0[off] + s1p[off] + gb0;
            float pre1 = a1[q] + ax1[off] + s3p[off] + gb1;
            float z = 1.f / (1.f + expf(-pre0));
            float r = 1.f / (1.f + expf(-pre1));
            float rh = r * hp[off];
            zp[off]  = z;
            rhp[off] = rh;
            xs[x * 65 + y] = rh;
        }
    }
    __syncthreads();
    // fused forward DFT of rh -> g_specRH (Y buffers alias dead Gr[0]/Gi[0])
    float* Yre = Gr[0];
    float* Yim = Gi[0];
    {
        int x = tid >> 2, kq = tid & 3;
        const float* row = xs + x * 65;
        float ar[4] = {0,0,0,0}, ai[4] = {0,0,0,0};
        int ii[4] = {0,0,0,0};
        #pragma unroll 8
        for (int y = 0; y < 64; y++) {
            float v = row[y];
            #pragma unroll
            for (int k = 0; k < 4; k++) {
                ar[k] += v * cs[ii[k]];
                ai[k] -= v * ss[ii[k]];
                ii[k] = (ii[k] + kq * 4 + k) & 63;
            }
        }
        #pragma unroll
        for (int k = 0; k < 4; k++) { Yre[x*17 + kq*4+k] = ar[k]; Yim[x*17 + kq*4+k] = ai[k]; }
    }
    __syncthreads();
    {
        int ky = tid & 15, kg = tid >> 4;
        float z0r=0, z0i=0, z1r=0, z1i=0;
        int i0 = 0, i1 = 0;
        #pragma unroll 8
        for (int x = 0; x < 64; x++) {
            float yr = Yre[x*17 + ky], yi = Yim[x*17 + ky];
            float c = cs[i0], s = ss[i0];
            z0r += yr*c + yi*s; z0i += yi*c - yr*s;
            c = cs[i1]; s = ss[i1];
            z1r += yr*c + yi*s; z1i += yi*c - yr*s;
            i0 = (i0 + kg) & 63; i1 = (i1 + kg + 48) & 63;
        }
        g_specRH[(size_t)(kg * 16 + ky) * 256 + img]        = make_float2(z0r, z0i);
        g_specRH[(size_t)((kg + 16) * 16 + ky) * 256 + img] = make_float2(z1r, z1i);
    }
}

// fused: mode-mix (w5) of specRH + inverse DFT + selu/blend + forward DFT of new h
__global__ __launch_bounds__(256) void k_invmix5(const float* __restrict__ gb, int t) {
    int img = blockIdx.x, tid = threadIdx.x;
    int b = img >> 6, o = img & 63;
    __shared__ float Zr[512], Zi[512];
    __shared__ __align__(16) float Gr[16 * 68];
    __shared__ __align__(16) float Gi[16 * 68];
    __shared__ float xs[64 * 65];
    __shared__ float cs[64], ss[64];
    if (tid < 64) { cs[tid] = g_c[tid]; ss[tid] = g_s[tid]; }
    #pragma unroll
    for (int mm = 0; mm < 2; mm++) {
        int m = tid + mm * 256;
        const float2* ih = g_specRH + (size_t)m * 256 + b * 64;
        const __nv_bfloat162* w5 = g_wmixB + ((size_t)(5 * 512 + m) * 64 + o) * 64;
        float ar = 0, ai = 0;
        #pragma unroll 8
        for (int i = 0; i < 64; i++) {
            float2 v = ih[i];
            float2 w = __bfloat1622float2(w5[i]);
            ar += v.x * w.x - v.y * w.y;
            ai += v.x * w.y + v.y * w.x;
        }
        Zr[m] = ar; Zi[m] = ai;
    }
    __syncthreads();
    {
        int ky = tid & 15, xg = tid >> 4, x0 = xg * 4;
        float gr[4] = {0,0,0,0}, gi[4] = {0,0,0,0};
        #pragma unroll 4
        for (int kxi = 0; kxi < 32; kxi++) {
            int kx = kxi + ((kxi >= 16) ? 32 : 0);
            float zr = Zr[kxi * 16 + ky], zi = Zi[kxi * 16 + ky];
            #pragma unroll
            for (int k = 0; k < 4; k++) {
                int id = (kx * (x0 + k)) & 63;
                float c = cs[id], s = ss[id];
                gr[k] += zr * c - zi * s;
                gi[k] += zr * s + zi * c;
            }
        }
        #pragma unroll
        for (int k = 0; k < 4; k++) { Gr[ky*68 + x0+k] = gr[k]; Gi[ky*68 + x0+k] = gi[k]; }
    }
    __syncthreads();
    {
        int y = tid & 63, xq = tid >> 6;
        float acc[16];
        #pragma unroll
        for (int q = 0; q < 16; q++) acc[q] = 0.f;
        for (int ky = 0; ky < 16; ky++) {
            int id = (ky * y) & 63;
            float c = cs[id], s = ss[id];
            const float4* a4 = (const float4*)(Gr + ky * 68 + xq * 16);
            const float4* b4 = (const float4*)(Gi + ky * 68 + xq * 16);
            #pragma unroll
            for (int q = 0; q < 4; q++) {
                float4 a = a4[q], bb = b4[q];
                acc[q*4+0] += a.x * c - bb.x * s;
                acc[q*4+1] += a.y * c - bb.y * s;
                acc[q*4+2] += a.z * c - bb.z * s;
                acc[q*4+3] += a.w * c - bb.w * s;
            }
        }
        float gb2 = gb[2];
        int bt = b * 8 + t;
        const float* ax2 = g_Ax + ((size_t)(2 * 32 + bt) * 64 + o) * HW;
        const float* s5p = g_S5 + ((size_t)b * 64 + o) * HW;
        const float* zp  = g_z + (size_t)img * HW;
        float* hp = g_h + (size_t)img * HW;
        const float SC = 1.0507009873554805f, AL = 1.6732632423543772f;
        #pragma unroll
        for (int q = 0; q < 16; q++) {
            int x = xq * 16 + q;
            int off = x * 64 + y;
            float v = acc[q] + ax2[off] + s5p[off] + gb2;
            float hh = (v > 0.f) ? SC * v : SC * AL * (expf(v) - 1.f);
            float z = zp[off], h = hp[off];
            float hn = (1.f - z) * h + z * hh;
            hp[off] = hn;
            xs[x * 65 + y] = hn;
        }
    }
    __syncthreads();
    // fused forward DFT of new h -> g_specH
    float* Yre = Gr;
    float* Yim = Gi;
    {
        int x = tid >> 2, kq = tid & 3;
        const float* row = xs + x * 65;
        float ar[4] = {0,0,0,0}, ai[4] = {0,0,0,0};
        int ii[4] = {0,0,0,0};
        #pragma unroll 8
        for (int y = 0; y < 64; y++) {
            float v = row[y];
            #pragma unroll
            for (int k = 0; k < 4; k++) {
                ar[k] += v * cs[ii[k]];
                ai[k] -= v * ss[ii[k]];
                ii[k] = (ii[k] + kq * 4 + k) & 63;
            }
        }
        #pragma unroll
        for (int k = 0; k < 4; k++) { Yre[x*17 + kq*4+k] = ar[k]; Yim[x*17 + kq*4+k] = ai[k]; }
    }
    __syncthreads();
    {
        int ky = tid & 15, kg = tid >> 4;
        float z0r=0, z0i=0, z1r=0, z1i=0;
        int i0 = 0, i1 = 0;
        #pragma unroll 8
        for (int x = 0; x < 64; x++) {
            float yr = Yre[x*17 + ky], yi = Yim[x*17 + ky];
            float c = cs[i0], s = ss[i0];
            z0r += yr*c + yi*s; z0i += yi*c - yr*s;
            c = cs[i1]; s = ss[i1];
            z1r += yr*c + yi*s; z1i += yi*c - yr*s;
            i0 = (i0 + kg) & 63; i1 = (i1 + kg + 48) & 63;
        }
        g_specH[(size_t)(kg * 16 + ky) * 256 + img]        = make_float2(z0r, z0i);
        g_specH[(size_t)((kg + 16) * 16 + ky) * 256 + img] = make_float2(z1r, z1i);
    }
}

__global__ void k_copy(float* __restrict__ out) {
    int idx = blockIdx.x * 256 + threadIdx.x;
    out[idx] = g_h[idx];
}

extern "C" void kernel_launch(void* const* d_in, const int* in_sizes, int n_in,
                              void* d_out, int out_size) {
    const float* x   = (const float*)d_in[0];
    const float* sw1 = (const float*)d_in[1];
    const float* sw2 = (const float*)d_in[2];
    const float* skw = (const float*)d_in[3];
    const float* gb  = (const float*)d_in[4];
    const float* bh  = (const float*)d_in[5];
    float* out = (float*)d_out;

    float2 *pSpecX, *pSpecH;
    float *pH;
    cudaGetSymbolAddress((void**)&pSpecX, g_specX);
    cudaGetSymbolAddress((void**)&pSpecH, g_specH);
    cudaGetSymbolAddress((void**)&pH, g_h);

    static cudaStream_t s1 = nullptr, s2 = nullptr;
    static cudaEvent_t e0, e1, e2;
    if (!s1) {
        cudaStreamCreateWithFlags(&s1, cudaStreamNonBlocking);
        cudaStreamCreateWithFlags(&s2, cudaStreamNonBlocking);
        cudaEventCreateWithFlags(&e0, cudaEventDisableTiming);
        cudaEventCreateWithFlags(&e1, cudaEventDisableTiming);
        cudaEventCreateWithFlags(&e2, cudaEventDisableTiming);
    }

    k_twiddle<<<1, 64>>>();
    cudaEventRecord(e0, 0);
    cudaStreamWaitEvent(s1, e0, 0);
    cudaStreamWaitEvent(s2, e0, 0);

    k_wtransB<<<dim3(8, 64, 6), 256>>>(sw1, sw2);            // default stream

    k_skipx<<<dim3(64, 32, 3), 256, 0, s1>>>(x, skw);
    k_fwd<<<2048, 256, 0, s1>>>(x, pSpecX, 2048);
    cudaEventRecord(e1, s1);

    k_hinit<<<4096, 256, 0, s2>>>(bh);
    k_fwd<<<256, 256, 0, s2>>>(pH, pSpecH, 256);
    k_hskip13<<<dim3(64, 4), 256, 0, s2>>>(skw);
    cudaEventRecord(e2, s2);

    cudaStreamWaitEvent(0, e1, 0);
    k_mix32<<<dim3(512, 3), 256>>>();
    k_invPre<<<dim3(2048, 3), 256>>>();
    cudaStreamWaitEvent(0, e2, 0);

    for (int t = 0; t < 8; t++) {
        k_invmixZR<<<256, 256>>>(gb, t);         // z, rh, specRH
        k_skip5<<<dim3(64, 4), 256>>>(skw);      // S5
        k_invmix5<<<256, 256>>>(gb, t);          // new h, specH
        if (t < 7) k_hskip13<<<dim3(64, 4), 256>>>(skw);
    }
    k_copy<<<4096, 256>>>(out);
}

// round 11
// speedup vs baseline: 1.8359x; 1.8359x over previous
#include <cuda_runtime.h>
#include <cuda_bf16.h>

#define HW 4096
#define NM 512

__device__ float  g_c[64], g_s[64];
__device__ float2 g_wmix[6 * NM * 4096];      // [j][m][i*64+o], scaled c_ky/4096
__device__ float2 g_specX[NM * 2048];         // [m][bt*64+c]
__device__ float2 g_specB[3 * NM * 2048];     // [jj][m][bt*64+o]
__device__ float2 g_specH[NM * 256];
__device__ float2 g_specF[2 * NM * 256];
__device__ float  g_Ax[3 * 32 * 64 * HW];     // [jj][bt][o][p]  (skip(x)+spectral(x))
__device__ float  g_S13[2 * 4 * 64 * HW];     // [w][b][o][p]  h-skips (skw1, skw3)
__device__ float  g_S5[4 * 64 * HW];          // rh-skip (skw5)
__device__ float  g_z[4 * 64 * HW];
__device__ float  g_rh[4 * 64 * HW];
__device__ float  g_h[4 * 64 * HW];

__global__ void k_twiddle() {
    int n = threadIdx.x;
    float s, c;
    sincospif(n * (1.0f / 32.0f), &s, &c);
    g_c[n] = c; g_s[n] = s;
}

// sw[j][i][o][kx][ky][2] -> g_wmix[j][m][i*64+o], m = kxi*16+ky
__global__ __launch_bounds__(256) void k_wtrans(const float* __restrict__ sw1,
                                                const float* __restrict__ sw2) {
    int bx = blockIdx.x;
    int j = bx >> 9, i = (bx >> 3) & 63, o0 = (bx & 7) * 8, tid = threadIdx.x;
    __shared__ float t1[4096], t2[4096];
    const float* s1 = sw1 + ((size_t)((j * 64 + i) * 64) + o0) * 512;
    const float* s2 = sw2 + ((size_t)((j * 64 + i) * 64) + o0) * 512;
    for (int idx = tid; idx < 4096; idx += 256) { t1[idx] = s1[idx]; t2[idx] = s2[idx]; }
    __syncthreads();
    float2* dst = g_wmix + (size_t)j * NM * 4096 + i * 64 + o0;
    for (int idx = tid; idx < NM * 8; idx += 256) {
        int m = idx >> 3, oo = idx & 7;
        int kxi = m >> 4, ky = m & 15;
        float f = (ky == 0 ? 1.0f : 2.0f) * (1.0f / 4096.0f);
        const float* tt = (kxi < 16) ? t1 : t2;
        int kk = (kxi < 16) ? kxi : (kxi - 16);
        float re = tt[oo * 512 + kk * 32 + ky * 2];
        float im = tt[oo * 512 + kk * 32 + ky * 2 + 1];
        dst[(size_t)m * 4096 + oo] = make_float2(re * f, im * f);
    }
}

__global__ void k_hinit(const float* __restrict__ bh) {
    float v = bh[0];
    int idx = blockIdx.x * 256 + threadIdx.x;
    g_h[idx] = v;
}

// partial forward DFT of one 64x64 image -> spec[m][img], m=kxi*16+ky
__global__ __launch_bounds__(256) void k_fwd(const float* __restrict__ in,
                                             float2* __restrict__ spec, int nimg) {
    __shared__ float xs[64 * 65];
    __shared__ float Yre[64 * 17], Yim[64 * 17];
    __shared__ float cs[64], ss[64];
    int tid = threadIdx.x, img = blockIdx.x;
    if (tid < 64) { cs[tid] = g_c[tid]; ss[tid] = g_s[tid]; }
    const float* src = in + (size_t)img * HW;
    for (int idx = tid; idx < HW; idx += 256)
        xs[(idx >> 6) * 65 + (idx & 63)] = src[idx];
    __syncthreads();
    {
        int x = tid >> 2, kq = tid & 3;
        const float* row = xs + x * 65;
        float ar[4] = {0,0,0,0}, ai[4] = {0,0,0,0};
        int ii[4] = {0,0,0,0};
        #pragma unroll 8
        for (int y = 0; y < 64; y++) {
            float v = row[y];
            #pragma unroll
            for (int k = 0; k < 4; k++) {
                ar[k] += v * cs[ii[k]];
                ai[k] -= v * ss[ii[k]];
                ii[k] = (ii[k] + kq * 4 + k) & 63;
            }
        }
        #pragma unroll
        for (int k = 0; k < 4; k++) { Yre[x*17 + kq*4+k] = ar[k]; Yim[x*17 + kq*4+k] = ai[k]; }
    }
    __syncthreads();
    {
        int ky = tid & 15, kg = tid >> 4;
        float z0r=0, z0i=0, z1r=0, z1i=0;
        int i0 = 0, i1 = 0;
        #pragma unroll 8
        for (int x = 0; x < 64; x++) {
            float yr = Yre[x*17 + ky], yi = Yim[x*17 + ky];
            float c = cs[i0], s = ss[i0];
            z0r += yr*c + yi*s; z0i += yi*c - yr*s;
            c = cs[i1]; s = ss[i1];
            z1r += yr*c + yi*s; z1i += yi*c - yr*s;
            i0 = (i0 + kg) & 63; i1 = (i1 + kg + 48) & 63;
        }
        spec[(size_t)(kg * 16 + ky) * nimg + img]        = make_float2(z0r, z0i);
        spec[(size_t)((kg + 16) * 16 + ky) * nimg + img] = make_float2(z1r, z1i);
    }
}

// mode mix, 32-image precompute
__global__ __launch_bounds__(256) void k_mix32() {
    int m = blockIdx.x, jj = blockIdx.y, tid = threadIdx.x;
    const float2* W = g_wmix + ((size_t)(2 * jj) * NM + m) * 4096;
    __shared__ float2 ins[2048];
    __shared__ float2 ws[4096];
    for (int idx = tid; idx < 2048; idx += 256) ins[idx] = g_specX[(size_t)m * 2048 + idx];
    for (int idx = tid; idx < 4096; idx += 256) ws[idx] = W[idx];
    __syncthreads();
    int o = tid & 63, bq = tid >> 6;
    float2 acc[8];
    #pragma unroll
    for (int g = 0; g < 8; g++) acc[g] = make_float2(0.f, 0.f);
    for (int i = 0; i < 64; i++) {
        float2 wv = ws[i * 64 + o];
        #pragma unroll
        for (int g = 0; g < 8; g++) {
            float2 iv = ins[(g * 4 + bq) * 64 + i];
            acc[g].x += iv.x * wv.x - iv.y * wv.y;
            acc[g].y += iv.x * wv.y + iv.y * wv.x;
        }
    }
    float2* outp = g_specB + (size_t)jj * NM * 2048 + (size_t)m * 2048;
    #pragma unroll
    for (int g = 0; g < 8; g++) outp[(g * 4 + bq) * 64 + o] = acc[g];
}

// mode mix for 4 images (in-loop)
__global__ __launch_bounds__(256) void k_mix4(const float2* __restrict__ inSpec,
                                              float2* __restrict__ outSpec,
                                              int wa, int wb) {
    int m = blockIdx.x, jj = blockIdx.y, tid = threadIdx.x;
    int w = jj ? wb : wa;
    const float2* W = g_wmix + ((size_t)w * NM + m) * 4096;
    __shared__ float2 ins[256];
    ins[tid] = inSpec[(size_t)m * 256 + tid];
    __syncthreads();
    int o = tid & 63, b = tid >> 6;
    float2 acc = make_float2(0.f, 0.f);
    #pragma unroll 8
    for (int i = 0; i < 64; i++) {
        float2 wv = __ldg(&W[i * 64 + o]);
        float2 iv = ins[b * 64 + i];
        acc.x += iv.x * wv.x - iv.y * wv.y;
        acc.y += iv.x * wv.y + iv.y * wv.x;
    }
    outSpec[(size_t)jj * NM * 256 + (size_t)m * 256 + tid] = acc;
}

// precompute inverse: g_Ax[jj] += irfft(specB[jj])
__global__ __launch_bounds__(256) void k_invPre() {
    int img = blockIdx.x, jj = blockIdx.y, tid = threadIdx.x;
    const float2* spec = g_specB + (size_t)jj * NM * 2048;
    __shared__ float Zr[512], Zi[512];
    __shared__ __align__(16) float Gr[16 * 68];
    __shared__ __align__(16) float Gi[16 * 68];
    __shared__ float cs[64], ss[64];
    if (tid < 64) { cs[tid] = g_c[tid]; ss[tid] = g_s[tid]; }
    for (int idx = tid; idx < 512; idx += 256) {
        float2 v = spec[(size_t)idx * 2048 + img];
        Zr[idx] = v.x; Zi[idx] = v.y;
    }
    __syncthreads();
    {
        int ky = tid & 15, xg = tid >> 4, x0 = xg * 4;
        float gr[4] = {0,0,0,0}, gi[4] = {0,0,0,0};
        #pragma unroll 4
        for (int kxi = 0; kxi < 32; kxi++) {
            int kx = kxi + ((kxi >= 16) ? 32 : 0);
            float zr = Zr[kxi * 16 + ky], zi = Zi[kxi * 16 + ky];
            #pragma unroll
            for (int k = 0; k < 4; k++) {
                int id = (kx * (x0 + k)) & 63;
                float c = cs[id], s = ss[id];
                gr[k] += zr * c - zi * s;
                gi[k] += zr * s + zi * c;
            }
        }
        #pragma unroll
        for (int k = 0; k < 4; k++) { Gr[ky*68 + x0+k] = gr[k]; Gi[ky*68 + x0+k] = gi[k]; }
    }
    __syncthreads();
    {
        int y = tid & 63, xq = tid >> 6;
        float acc[16];
        #pragma unroll
        for (int q = 0; q < 16; q++) acc[q] = 0.f;
        for (int ky = 0; ky < 16; ky++) {
            int id = (ky * y) & 63;
            float c = cs[id], s = ss[id];
            const float4* a4 = (const float4*)(Gr + ky * 68 + xq * 16);
            const float4* b4 = (const float4*)(Gi + ky * 68 + xq * 16);
            #pragma unroll
            for (int q = 0; q < 4; q++) {
                float4 a = a4[q], b = b4[q];
                acc[q*4+0] += a.x * c - b.x * s;
                acc[q*4+1] += a.y * c - b.y * s;
                acc[q*4+2] += a.z * c - b.z * s;
                acc[q*4+3] += a.w * c - b.w * s;
            }
        }
        float* outp = g_Ax + (size_t)jj * 32 * 64 * HW + (size_t)img * HW;
        #pragma unroll
        for (int q = 0; q < 16; q++) {
            int off = (xq * 16 + q) * 64 + y;
            outp[off] += acc[q];
        }
    }
}

// Ax[jj][bt][o][p] = sum_i x[bt][i][p] * skw[2jj][i][o]
__global__ __launch_bounds__(256) void k_skipx(const float* __restrict__ x,
                                               const float* __restrict__ skw) {
    int p0 = blockIdx.x * 64, bt = blockIdx.y, jj = blockIdx.z, tid = threadIdx.x;
    __shared__ __align__(16) float xs[4096];
    __shared__ __align__(16) float ws[4096];
    {
        float4* xs4 = (float4*)xs;
        float4* ws4 = (float4*)ws;
        const float4* wsrc = (const float4*)(skw + (size_t)(2 * jj) * 4096);
        for (int idx = tid; idx < 1024; idx += 256) {
            int c = idx >> 4, v = idx & 15;
            xs4[idx] = *(const float4*)(x + (size_t)(bt * 64 + c) * HW + p0 + v * 4);
            ws4[idx] = wsrc[idx];
        }
    }
    __syncthreads();
    int pi = (tid & 15) * 4, o0 = (tid >> 4) * 4;
    float4 a[4];
    #pragma unroll
    for (int k = 0; k < 4; k++) a[k] = make_float4(0.f, 0.f, 0.f, 0.f);
    #pragma unroll 4
    for (int i = 0; i < 64; i++) {
        float4 xv = *(const float4*)(xs + i * 64 + pi);
        float4 wv = *(const float4*)(ws + i * 64 + o0);
        a[0].x += wv.x*xv.x; a[0].y += wv.x*xv.y; a[0].z += wv.x*xv.z; a[0].w += wv.x*xv.w;
        a[1].x += wv.y*xv.x; a[1].y += wv.y*xv.y; a[1].z += wv.y*xv.z; a[1].w += wv.y*xv.w;
        a[2].x += wv.z*xv.x; a[2].y += wv.z*xv.y; a[2].z += wv.z*xv.z; a[2].w += wv.z*xv.w;
        a[3].x += wv.w*xv.x; a[3].y += wv.w*xv.y; a[3].z += wv.w*xv.z; a[3].w += wv.w*xv.w;
    }
    #pragma unroll
    for (int oi = 0; oi < 4; oi++)
        *(float4*)(g_Ax + ((size_t)(jj * 32 + bt) * 64 + o0 + oi) * HW + p0 + pi) = a[oi];
}

// S13[w][b][o][p] = sum_i h[b][i][p] * skw[1 or 3][i][o]
__global__ __launch_bounds__(256) void k_hskip13(const float* __restrict__ skw) {
    int p0 = blockIdx.x * 64, b = blockIdx.y, tid = threadIdx.x;
    __shared__ __align__(16) float hs[4096];
    __shared__ __align__(16) float w1s[4096];
    __shared__ __align__(16) float w3s[4096];
    {
        float4* h4 = (float4*)hs;
        float4* a4 = (float4*)w1s;
        float4* b4 = (float4*)w3s;
        const float4* w1src = (const float4*)(skw + 4096);
        const float4* w3src = (const float4*)(skw + 3 * 4096);
        for (int idx = tid; idx < 1024; idx += 256) {
            int c = idx >> 4, v = idx & 15;
            h4[idx] = *(const float4*)(g_h + (size_t)(b * 64 + c) * HW + p0 + v * 4);
            a4[idx] = w1src[idx];
            b4[idx] = w3src[idx];
        }
    }
    __syncthreads();
    int pi = (tid & 15) * 4, o0 = (tid >> 4) * 4;
    float4 a1[4], a3[4];
    #pragma unroll
    for (int k = 0; k < 4; k++) { a1[k] = make_float4(0,0,0,0); a3[k] = make_float4(0,0,0,0); }
    #pragma unroll 2
    for (int i = 0; i < 64; i++) {
        float4 xv = *(const float4*)(hs + i * 64 + pi);
        float4 wa = *(const float4*)(w1s + i * 64 + o0);
        float4 wb = *(const float4*)(w3s + i * 64 + o0);
        a1[0].x += wa.x*xv.x; a1[0].y += wa.x*xv.y; a1[0].z += wa.x*xv.z; a1[0].w += wa.x*xv.w;
        a1[1].x += wa.y*xv.x; a1[1].y += wa.y*xv.y; a1[1].z += wa.y*xv.z; a1[1].w += wa.y*xv.w;
        a1[2].x += wa.z*xv.x; a1[2].y += wa.z*xv.y; a1[2].z += wa.z*xv.z; a1[2].w += wa.z*xv.w;
        a1[3].x += wa.w*xv.x; a1[3].y += wa.w*xv.y; a1[3].z += wa.w*xv.z; a1[3].w += wa.w*xv.w;
        a3[0].x += wb.x*xv.x; a3[0].y += wb.x*xv.y; a3[0].z += wb.x*xv.z; a3[0].w += wb.x*xv.w;
        a3[1].x += wb.y*xv.x; a3[1].y += wb.y*xv.y; a3[1].z += wb.y*xv.z; a3[1].w += wb.y*xv.w;
        a3[2].x += wb.z*xv.x; a3[2].y += wb.z*xv.y; a3[2].z += wb.z*xv.z; a3[2].w += wb.z*xv.w;
        a3[3].x += wb.w*xv.x; a3[3].y += wb.w*xv.y; a3[3].z += wb.w*xv.z; a3[3].w += wb.w*xv.w;
    }
    #pragma unroll
    for (int oi = 0; oi < 4; oi++) {
        *(float4*)(g_S13 + ((size_t)(0 * 4 + b) * 64 + o0 + oi) * HW + p0 + pi) = a1[oi];
        *(float4*)(g_S13 + ((size_t)(1 * 4 + b) * 64 + o0 + oi) * HW + p0 + pi) = a3[oi];
    }
}

// S5[b][o][p] = sum_i rh[b][i][p] * skw[5][i][o]
__global__ __launch_bounds__(256) void k_skip5(const float* __restrict__ skw) {
    int p0 = blockIdx.x * 64, b = blockIdx.y, tid = threadIdx.x;
    __shared__ __align__(16) float rs[4096];
    __shared__ __align__(16) float ws[4096];
    {
        float4* r4 = (float4*)rs;
        float4* w4 = (float4*)ws;
        const float4* wsrc = (const float4*)(skw + 5 * 4096);
        for (int idx = tid; idx < 1024; idx += 256) {
            int c = idx >> 4, v = idx & 15;
            r4[idx] = *(const float4*)(g_rh + (size_t)(b * 64 + c) * HW + p0 + v * 4);
            w4[idx] = wsrc[idx];
        }
    }
    __syncthreads();
    int pi = (tid & 15) * 4, o0 = (tid >> 4) * 4;
    float4 a[4];
    #pragma unroll
    for (int k = 0; k < 4; k++) a[k] = make_float4(0.f, 0.f, 0.f, 0.f);
    #pragma unroll 4
    for (int i = 0; i < 64; i++) {
        float4 xv = *(const float4*)(rs + i * 64 + pi);
        float4 wv = *(const float4*)(ws + i * 64 + o0);
        a[0].x += wv.x*xv.x; a[0].y += wv.x*xv.y; a[0].z += wv.x*xv.z; a[0].w += wv.x*xv.w;
        a[1].x += wv.y*xv.x; a[1].y += wv.y*xv.y; a[1].z += wv.y*xv.z; a[1].w += wv.y*xv.w;
        a[2].x += wv.z*xv.x; a[2].y += wv.z*xv.y; a[2].z += wv.z*xv.z; a[2].w += wv.z*xv.w;
        a[3].x += wv.w*xv.x; a[3].y += wv.w*xv.y; a[3].z += wv.w*xv.z; a[3].w += wv.w*xv.w;
    }
    #pragma unroll
    for (int oi = 0; oi < 4; oi++)
        *(float4*)(g_S5 + ((size_t)b * 64 + o0 + oi) * HW + p0 + pi) = a[oi];
}

// inverse DFT of z/r spectra + gate epilogue + FUSED forward DFT of rh
__global__ __launch_bounds__(256) void k_invzrF(const float* __restrict__ gb, int t) {
    int img = blockIdx.x, tid = threadIdx.x;
    int b = img >> 6, o = img & 63;
    __shared__ float Zr[2][512], Zi[2][512];
    __shared__ __align__(16) float Gr[2][16 * 68];
    __shared__ __align__(16) float Gi[2][16 * 68];
    __shared__ float xs[64 * 65];
    __shared__ float cs[64], ss[64];
    if (tid < 64) { cs[tid] = g_c[tid]; ss[tid] = g_s[tid]; }
    #pragma unroll
    for (int jj = 0; jj < 2; jj++)
        for (int idx = tid; idx < 512; idx += 256) {
            float2 v = g_specF[(size_t)jj * NM * 256 + (size_t)idx * 256 + img];
            Zr[jj][idx] = v.x; Zi[jj][idx] = v.y;
        }
    __syncthreads();
    {
        int ky = tid & 15, xg = tid >> 4, x0 = xg * 4;
        #pragma unroll
        for (int jj = 0; jj < 2; jj++) {
            float gr[4] = {0,0,0,0}, gi[4] = {0,0,0,0};
            #pragma unroll 4
            for (int kxi = 0; kxi < 32; kxi++) {
                int kx = kxi + ((kxi >= 16) ? 32 : 0);
                float zr = Zr[jj][kxi * 16 + ky], zi = Zi[jj][kxi * 16 + ky];
                #pragma unroll
                for (int k = 0; k < 4; k++) {
                    int id = (kx * (x0 + k)) & 63;
                    float c = cs[id], s = ss[id];
                    gr[k] += zr * c - zi * s;
                    gi[k] += zr * s + zi * c;
                }
            }
            #pragma unroll
            for (int k = 0; k < 4; k++) { Gr[jj][ky*68 + x0+k] = gr[k]; Gi[jj][ky*68 + x0+k] = gi[k]; }
        }
    }
    __syncthreads();
    {
        int y = tid & 63, xq = tid >> 6;
        float a0[16], a1[16];
        #pragma unroll
        for (int q = 0; q < 16; q++) { a0[q] = 0.f; a1[q] = 0.f; }
        for (int ky = 0; ky < 16; ky++) {
            int id = (ky * y) & 63;
            float c = cs[id], s = ss[id];
            const float4* ar4 = (const float4*)(Gr[0] + ky * 68 + xq * 16);
            const float4* ai4 = (const float4*)(Gi[0] + ky * 68 + xq * 16);
            const float4* br4 = (const float4*)(Gr[1] + ky * 68 + xq * 16);
            const float4* bi4 = (const float4*)(Gi[1] + ky * 68 + xq * 16);
            #pragma unroll
            for (int q = 0; q < 4; q++) {
                float4 xr = ar4[q], xi = ai4[q];
                a0[q*4+0] += xr.x * c - xi.x * s;
                a0[q*4+1] += xr.y * c - xi.y * s;
                a0[q*4+2] += xr.z * c - xi.z * s;
                a0[q*4+3] += xr.w * c - xi.w * s;
                float4 yr = br4[q], yi = bi4[q];
                a1[q*4+0] += yr.x * c - yi.x * s;
                a1[q*4+1] += yr.y * c - yi.y * s;
                a1[q*4+2] += yr.z * c - yi.z * s;
                a1[q*4+3] += yr.w * c - yi.w * s;
            }
        }
        float gb0 = gb[0], gb1 = gb[1];
        int bt = b * 8 + t;
        const float* ax0 = g_Ax + ((size_t)(0 * 32 + bt) * 64 + o) * HW;
        const float* ax1 = g_Ax + ((size_t)(1 * 32 + bt) * 64 + o) * HW;
        const float* s1p = g_S13 + ((size_t)(0 * 4 + b) * 64 + o) * HW;
        const float* s3p = g_S13 + ((size_t)(1 * 4 + b) * 64 + o) * HW;
        const float* hp  = g_h + (size_t)img * HW;
        float* zp  = g_z + (size_t)img * HW;
        float* rhp = g_rh + (size_t)img * HW;
        #pragma unroll
        for (int q = 0; q < 16; q++) {
            int x = xq * 16 + q;
            int off = x * 64 + y;
            float pre0 = a0[q] + ax0[off] + s1p[off] + gb0;
            float pre1 = a1[q] + ax1[off] + s3p[off] + gb1;
            float z = 1.f / (1.f + expf(-pre0));
            float r = 1.f / (1.f + expf(-pre1));
            float rh = r * hp[off];
            zp[off]  = z;
            rhp[off] = rh;
            xs[x * 65 + y] = rh;
        }
    }
    __syncthreads();
    float* Yre = Gr[0];
    float* Yim = Gi[0];
    {
        int x = tid >> 2, kq = tid & 3;
        const float* row = xs + x * 65;
        float ar[4] = {0,0,0,0}, ai[4] = {0,0,0,0};
        int ii[4] = {0,0,0,0};
        #pragma unroll 8
        for (int y = 0; y < 64; y++) {
            float v = row[y];
            #pragma unroll
            for (int k = 0; k < 4; k++) {
                ar[k] += v * cs[ii[k]];
                ai[k] -= v * ss[ii[k]];
                ii[k] = (ii[k] + kq * 4 + k) & 63;
            }
        }
        #pragma unroll
        for (int k = 0; k < 4; k++) { Yre[x*17 + kq*4+k] = ar[k]; Yim[x*17 + kq*4+k] = ai[k]; }
    }
    __syncthreads();
    {
        int ky = tid & 15, kg = tid >> 4;
        float z0r=0, z0i=0, z1r=0, z1i=0;
        int i0 = 0, i1 = 0;
        #pragma unroll 8
        for (int x = 0; x < 64; x++) {
            float yr = Yre[x*17 + ky], yi = Yim[x*17 + ky];
            float c = cs[i0], s = ss[i0];
            z0r += yr*c + yi*s; z0i += yi*c - yr*s;
            c = cs[i1]; s = ss[i1];
            z1r += yr*c + yi*s; z1i += yi*c - yr*s;
            i0 = (i0 + kg) & 63; i1 = (i1 + kg + 48) & 63;
        }
        g_specH[(size_t)(kg * 16 + ky) * 256 + img]        = make_float2(z0r, z0i);
        g_specH[(size_t)((kg + 16) * 16 + ky) * 256 + img] = make_float2(z1r, z1i);
    }
}

// inverse DFT of h_hat + selu + blend -> new h, FUSED forward DFT of new h
__global__ __launch_bounds__(256) void k_inv5F(const float* __restrict__ gb, int t) {
    int img = blockIdx.x, tid = threadIdx.x;
    int b = img >> 6, o = img & 63;
    __shared__ float Zr[512], Zi[512];
    __shared__ __align__(16) float Gr[16 * 68];
    __shared__ __align__(16) float Gi[16 * 68];
    __shared__ float xs[64 * 65];
    __shared__ float cs[64], ss[64];
    if (tid < 64) { cs[tid] = g_c[tid]; ss[tid] = g_s[tid]; }
    for (int idx = tid; idx < 512; idx += 256) {
        float2 v = g_specF[(size_t)idx * 256 + img];
        Zr[idx] = v.x; Zi[idx] = v.y;
    }
    __syncthreads();
    {
        int ky = tid & 15, xg = tid >> 4, x0 = xg * 4;
        float gr[4] = {0,0,0,0}, gi[4] = {0,0,0,0};
        #pragma unroll 4
        for (int kxi = 0; kxi < 32; kxi++) {
            int kx = kxi + ((kxi >= 16) ? 32 : 0);
            float zr = Zr[kxi * 16 + ky], zi = Zi[kxi * 16 + ky];
            #pragma unroll
            for (int k = 0; k < 4; k++) {
                int id = (kx * (x0 + k)) & 63;
                float c = cs[id], s = ss[id];
                gr[k] += zr * c - zi * s;
                gi[k] += zr * s + zi * c;
            }
        }
        #pragma unroll
        for (int k = 0; k < 4; k++) { Gr[ky*68 + x0+k] = gr[k]; Gi[ky*68 + x0+k] = gi[k]; }
    }
    __syncthreads();
    {
        int y = tid & 63, xq = tid >> 6;
        float acc[16];
        #pragma unroll
        for (int q = 0; q < 16; q++) acc[q] = 0.f;
        for (int ky = 0; ky < 16; ky++) {
            int id = (ky * y) & 63;
            float c = cs[id], s = ss[id];
            const float4* a4 = (const float4*)(Gr + ky * 68 + xq * 16);
            const float4* b4 = (const float4*)(Gi + ky * 68 + xq * 16);
            #pragma unroll
            for (int q = 0; q < 4; q++) {
                float4 a = a4[q], bb = b4[q];
                acc[q*4+0] += a.x * c - bb.x * s;
                acc[q*4+1] += a.y * c - bb.y * s;
                acc[q*4+2] += a.z * c - bb.z * s;
                acc[q*4+3] += a.w * c - bb.w * s;
            }
        }
        float gb2 = gb[2];
        int bt = b * 8 + t;
        const float* ax2 = g_Ax + ((size_t)(2 * 32 + bt) * 64 + o) * HW;
        const float* s5p = g_S5 + ((size_t)b * 64 + o) * HW;
        const float* zp  = g_z + (size_t)img * HW;
        float* hp = g_h + (size_t)img * HW;
        const float SC = 1.0507009873554805f, AL = 1.6732632423543772f;
        #pragma unroll
        for (int q = 0; q < 16; q++) {
            int x = xq * 16 + q;
            int off = x * 64 + y;
            float v = acc[q] + ax2[off] + s5p[off] + gb2;
            float hh = (v > 0.f) ? SC * v : SC * AL * (expf(v) - 1.f);
            float z = zp[off], h = hp[off];
            float hn = (1.f - z) * h + z * hh;
            hp[off] = hn;
            xs[x * 65 + y] = hn;
        }
    }
    __syncthreads();
    float* Yre = Gr;
    float* Yim = Gi;
    {
        int x = tid >> 2, kq = tid & 3;
        const float* row = xs + x * 65;
        float ar[4] = {0,0,0,0}, ai[4] = {0,0,0,0};
        int ii[4] = {0,0,0,0};
        #pragma unroll 8
        for (int y = 0; y < 64; y++) {
            float v = row[y];
            #pragma unroll
            for (int k = 0; k < 4; k++) {
                ar[k] += v * cs[ii[k]];
                ai[k] -= v * ss[ii[k]];
                ii[k] = (ii[k] + kq * 4 + k) & 63;
            }
        }
        #pragma unroll
        for (int k = 0; k < 4; k++) { Yre[x*17 + kq*4+k] = ar[k]; Yim[x*17 + kq*4+k] = ai[k]; }
    }
    __syncthreads();
    {
        int ky = tid & 15, kg = tid >> 4;
        float z0r=0, z0i=0, z1r=0, z1i=0;
        int i0 = 0, i1 = 0;
        #pragma unroll 8
        for (int x = 0; x < 64; x++) {
            float yr = Yre[x*17 + ky], yi = Yim[x*17 + ky];
            float c = cs[i0], s = ss[i0];
            z0r += yr*c + yi*s; z0i += yi*c - yr*s;
            c = cs[i1]; s = ss[i1];
            z1r += yr*c + yi*s; z1i += yi*c - yr*s;
            i0 = (i0 + kg) & 63; i1 = (i1 + kg + 48) & 63;
        }
        g_specH[(size_t)(kg * 16 + ky) * 256 + img]        = make_float2(z0r, z0i);
        g_specH[(size_t)((kg + 16) * 16 + ky) * 256 + img] = make_float2(z1r, z1i);
    }
}

__global__ void k_copy(float* __restrict__ out) {
    int idx = blockIdx.x * 256 + threadIdx.x;
    out[idx] = g_h[idx];
}

extern "C" void kernel_launch(void* const* d_in, const int* in_sizes, int n_in,
                              void* d_out, int out_size) {
    const float* x   = (const float*)d_in[0];
    const float* sw1 = (const float*)d_in[1];
    const float* sw2 = (const float*)d_in[2];
    const float* skw = (const float*)d_in[3];
    const float* gb  = (const float*)d_in[4];
    const float* bh  = (const float*)d_in[5];
    float* out = (float*)d_out;

    float2 *pSpecX, *pSpecH, *pSpecF;
    float *pH;
    cudaGetSymbolAddress((void**)&pSpecX, g_specX);
    cudaGetSymbolAddress((void**)&pSpecH, g_specH);
    cudaGetSymbolAddress((void**)&pSpecF, g_specF);
    cudaGetSymbolAddress((void**)&pH, g_h);

    static cudaStream_t s1 = nullptr, s2 = nullptr;
    static cudaEvent_t e0, e1, e2;
    if (!s1) {
        cudaStreamCreateWithFlags(&s1, cudaStreamNonBlocking);
        cudaStreamCreateWithFlags(&s2, cudaStreamNonBlocking);
        cudaEventCreateWithFlags(&e0, cudaEventDisableTiming);
        cudaEventCreateWithFlags(&e1, cudaEventDisableTiming);
        cudaEventCreateWithFlags(&e2, cudaEventDisableTiming);
    }

    k_twiddle<<<1, 64>>>();
    cudaEventRecord(e0, 0);
    cudaStreamWaitEvent(s1, e0, 0);
    cudaStreamWaitEvent(s2, e0, 0);

    // default stream: weight transpose (bandwidth-bound, overlaps with s1/s2)
    k_wtrans<<<3072, 256>>>(sw1, sw2);

    // s1: x-dependent precompute
    k_skipx<<<dim3(64, 32, 3), 256, 0, s1>>>(x, skw);
    k_fwd<<<2048, 256, 0, s1>>>(x, pSpecX, 2048);
    cudaEventRecord(e1, s1);

    // s2: h0 branch
    k_hinit<<<4096, 256, 0, s2>>>(bh);
    k_fwd<<<256, 256, 0, s2>>>(pH, pSpecH, 256);
    k_hskip13<<<dim3(64, 4), 256, 0, s2>>>(skw);
    cudaEventRecord(e2, s2);

    // join: mix32 needs wtrans (default) + specX (e1); invPre needs mix32 + Ax (e1)
    cudaStreamWaitEvent(0, e1, 0);
    k_mix32<<<dim3(512, 3), 256>>>();
    k_invPre<<<dim3(2048, 3), 256>>>();
    cudaStreamWaitEvent(0, e2, 0);

    for (int t = 0; t < 8; t++) {
        k_mix4<<<dim3(512, 2), 256>>>(pSpecH, pSpecF, 1, 3);
        k_invzrF<<<256, 256>>>(gb, t);          // z, rh, specH(rh)
        k_skip5<<<dim3(64, 4), 256>>>(skw);
        k_mix4<<<dim3(512, 1), 256>>>(pSpecH, pSpecF, 5, 5);
        k_inv5F<<<256, 256>>>(gb, t);           // new h, specH(h')
        if (t < 7) k_hskip13<<<dim3(64, 4), 256>>>(skw);
    }
    k_copy<<<4096, 256>>>(out);
}

// round 15
// speedup vs baseline: 1.8967x; 1.0331x over previous
#include <cuda_runtime.h>
#include <cuda_bf16.h>

#define HW 4096
#define NM 512

__device__ float  g_c[64], g_s[64];
__device__ float2 g_wmix[6 * NM * 4096];      // [j][m][i*64+o], scaled c_ky/4096
__device__ float2 g_specX[NM * 2048];         // [m][bt*64+c]
__device__ float2 g_specB[3 * NM * 2048];     // [jj][m][bt*64+o]
__device__ float2 g_specH[NM * 256];
__device__ float2 g_specF[2 * NM * 256];
__device__ float  g_Ax[3 * 32 * 64 * HW];     // [jj][bt][o][p]  (skip(x)+spectral(x))
__device__ float  g_S13[2 * 4 * 64 * HW];     // [w][b][o][p]  h-skips (skw1, skw3)
__device__ float  g_S5[4 * 64 * HW];          // rh-skip (skw5)
__device__ float  g_z[4 * 64 * HW];
__device__ float  g_rh[4 * 64 * HW];
__device__ float  g_h[4 * 64 * HW];

__global__ void k_twiddle() {
    int n = threadIdx.x;
    float s, c;
    sincospif(n * (1.0f / 32.0f), &s, &c);
    g_c[n] = c; g_s[n] = s;
}

// sw[j][i][o][kx][ky][2] -> g_wmix[j][m][i*64+o], m = kxi*16+ky
__global__ __launch_bounds__(256) void k_wtrans(const float* __restrict__ sw1,
                                                const float* __restrict__ sw2) {
    int bx = blockIdx.x;
    int j = bx >> 9, i = (bx >> 3) & 63, o0 = (bx & 7) * 8, tid = threadIdx.x;
    __shared__ float t1[4096], t2[4096];
    const float* s1 = sw1 + ((size_t)((j * 64 + i) * 64) + o0) * 512;
    const float* s2 = sw2 + ((size_t)((j * 64 + i) * 64) + o0) * 512;
    for (int idx = tid; idx < 4096; idx += 256) { t1[idx] = s1[idx]; t2[idx] = s2[idx]; }
    __syncthreads();
    float2* dst = g_wmix + (size_t)j * NM * 4096 + i * 64 + o0;
    for (int idx = tid; idx < NM * 8; idx += 256) {
        int m = idx >> 3, oo = idx & 7;
        int kxi = m >> 4, ky = m & 15;
        float f = (ky == 0 ? 1.0f : 2.0f) * (1.0f / 4096.0f);
        const float* tt = (kxi < 16) ? t1 : t2;
        int kk = (kxi < 16) ? kxi : (kxi - 16);
        float re = tt[oo * 512 + kk * 32 + ky * 2];
        float im = tt[oo * 512 + kk * 32 + ky * 2 + 1];
        dst[(size_t)m * 4096 + oo] = make_float2(re * f, im * f);
    }
}

__global__ void k_hinit(const float* __restrict__ bh) {
    float v = bh[0];
    int idx = blockIdx.x * 256 + threadIdx.x;
    g_h[idx] = v;
}

// partial forward DFT of one 64x64 image -> spec[m][img], m=kxi*16+ky
__global__ __launch_bounds__(256) void k_fwd(const float* __restrict__ in,
                                             float2* __restrict__ spec, int nimg) {
    __shared__ float xs[64 * 65];
    __shared__ float Yre[64 * 17], Yim[64 * 17];
    __shared__ float cs[64], ss[64];
    int tid = threadIdx.x, img = blockIdx.x;
    if (tid < 64) { cs[tid] = g_c[tid]; ss[tid] = g_s[tid]; }
    const float* src = in + (size_t)img * HW;
    for (int idx = tid; idx < HW; idx += 256)
        xs[(idx >> 6) * 65 + (idx & 63)] = src[idx];
    __syncthreads();
    {
        int x = tid >> 2, kq = tid & 3;
        const float* row = xs + x * 65;
        float ar[4] = {0,0,0,0}, ai[4] = {0,0,0,0};
        int ii[4] = {0,0,0,0};
        #pragma unroll 8
        for (int y = 0; y < 64; y++) {
            float v = row[y];
            #pragma unroll
            for (int k = 0; k < 4; k++) {
                ar[k] += v * cs[ii[k]];
                ai[k] -= v * ss[ii[k]];
                ii[k] = (ii[k] + kq * 4 + k) & 63;
            }
        }
        #pragma unroll
        for (int k = 0; k < 4; k++) { Yre[x*17 + kq*4+k] = ar[k]; Yim[x*17 + kq*4+k] = ai[k]; }
    }
    __syncthreads();
    {
        int ky = tid & 15, kg = tid >> 4;
        float z0r=0, z0i=0, z1r=0, z1i=0;
        int i0 = 0, i1 = 0;
        #pragma unroll 8
        for (int x = 0; x < 64; x++) {
            float yr = Yre[x*17 + ky], yi = Yim[x*17 + ky];
            float c = cs[i0], s = ss[i0];
            z0r += yr*c + yi*s; z0i += yi*c - yr*s;
            c = cs[i1]; s = ss[i1];
            z1r += yr*c + yi*s; z1i += yi*c - yr*s;
            i0 = (i0 + kg) & 63; i1 = (i1 + kg + 48) & 63;
        }
        spec[(size_t)(kg * 16 + ky) * nimg + img]        = make_float2(z0r, z0i);
        spec[(size_t)((kg + 16) * 16 + ky) * nimg + img] = make_float2(z1r, z1i);
    }
}

// mode mix, 32-image precompute
__global__ __launch_bounds__(256) void k_mix32() {
    int m = blockIdx.x, jj = blockIdx.y, tid = threadIdx.x;
    const float2* W = g_wmix + ((size_t)(2 * jj) * NM + m) * 4096;
    __shared__ float2 ins[2048];
    __shared__ float2 ws[4096];
    for (int idx = tid; idx < 2048; idx += 256) ins[idx] = g_specX[(size_t)m * 2048 + idx];
    for (int idx = tid; idx < 4096; idx += 256) ws[idx] = W[idx];
    __syncthreads();
    int o = tid & 63, bq = tid >> 6;
    float2 acc[8];
    #pragma unroll
    for (int g = 0; g < 8; g++) acc[g] = make_float2(0.f, 0.f);
    for (int i = 0; i < 64; i++) {
        float2 wv = ws[i * 64 + o];
        #pragma unroll
        for (int g = 0; g < 8; g++) {
            float2 iv = ins[(g * 4 + bq) * 64 + i];
            acc[g].x += iv.x * wv.x - iv.y * wv.y;
            acc[g].y += iv.x * wv.y + iv.y * wv.x;
        }
    }
    float2* outp = g_specB + (size_t)jj * NM * 2048 + (size_t)m * 2048;
    #pragma unroll
    for (int g = 0; g < 8; g++) outp[(g * 4 + bq) * 64 + o] = acc[g];
}

// mode mix for 4 images (in-loop)
__global__ __launch_bounds__(256) void k_mix4(const float2* __restrict__ inSpec,
                                              float2* __restrict__ outSpec,
                                              int wa, int wb) {
    int m = blockIdx.x, jj = blockIdx.y, tid = threadIdx.x;
    int w = jj ? wb : wa;
    const float2* W = g_wmix + ((size_t)w * NM + m) * 4096;
    __shared__ float2 ins[256];
    ins[tid] = inSpec[(size_t)m * 256 + tid];
    __syncthreads();
    int o = tid & 63, b = tid >> 6;
    float2 acc = make_float2(0.f, 0.f);
    #pragma unroll 8
    for (int i = 0; i < 64; i++) {
        float2 wv = __ldg(&W[i * 64 + o]);
        float2 iv = ins[b * 64 + i];
        acc.x += iv.x * wv.x - iv.y * wv.y;
        acc.y += iv.x * wv.y + iv.y * wv.x;
    }
    outSpec[(size_t)jj * NM * 256 + (size_t)m * 256 + tid] = acc;
}

// precompute inverse: g_Ax[jj] += irfft(specB[jj])
__global__ __launch_bounds__(256) void k_invPre() {
    int img = blockIdx.x, jj = blockIdx.y, tid = threadIdx.x;
    const float2* spec = g_specB + (size_t)jj * NM * 2048;
    __shared__ float Zr[512], Zi[512];
    __shared__ __align__(16) float Gr[16 * 68];
    __shared__ __align__(16) float Gi[16 * 68];
    __shared__ float cs[64], ss[64];
    if (tid < 64) { cs[tid] = g_c[tid]; ss[tid] = g_s[tid]; }
    for (int idx = tid; idx < 512; idx += 256) {
        float2 v = spec[(size_t)idx * 2048 + img];
        Zr[idx] = v.x; Zi[idx] = v.y;
    }
    __syncthreads();
    {
        int ky = tid & 15, xg = tid >> 4, x0 = xg * 4;
        float gr[4] = {0,0,0,0}, gi[4] = {0,0,0,0};
        #pragma unroll 4
        for (int kxi = 0; kxi < 32; kxi++) {
            int kx = kxi + ((kxi >= 16) ? 32 : 0);
            float zr = Zr[kxi * 16 + ky], zi = Zi[kxi * 16 + ky];
            #pragma unroll
            for (int k = 0; k < 4; k++) {
                int id = (kx * (x0 + k)) & 63;
                float c = cs[id], s = ss[id];
                gr[k] += zr * c - zi * s;
                gi[k] += zr * s + zi * c;
            }
        }
        #pragma unroll
        for (int k = 0; k < 4; k++) { Gr[ky*68 + x0+k] = gr[k]; Gi[ky*68 + x0+k] = gi[k]; }
    }
    __syncthreads();
    {
        int y = tid & 63, xq = tid >> 6;
        float acc[16];
        #pragma unroll
        for (int q = 0; q < 16; q++) acc[q] = 0.f;
        for (int ky = 0; ky < 16; ky++) {
            int id = (ky * y) & 63;
            float c = cs[id], s = ss[id];
            const float4* a4 = (const float4*)(Gr + ky * 68 + xq * 16);
            const float4* b4 = (const float4*)(Gi + ky * 68 + xq * 16);
            #pragma unroll
            for (int q = 0; q < 4; q++) {
                float4 a = a4[q], b = b4[q];
                acc[q*4+0] += a.x * c - b.x * s;
                acc[q*4+1] += a.y * c - b.y * s;
                acc[q*4+2] += a.z * c - b.z * s;
                acc[q*4+3] += a.w * c - b.w * s;
            }
        }
        float* outp = g_Ax + (size_t)jj * 32 * 64 * HW + (size_t)img * HW;
        #pragma unroll
        for (int q = 0; q < 16; q++) {
            int off = (xq * 16 + q) * 64 + y;
            outp[off] += acc[q];
        }
    }
}

// Ax[jj][bt][o][p] = sum_i x[bt][i][p] * skw[2jj][i][o]
__global__ __launch_bounds__(256) void k_skipx(const float* __restrict__ x,
                                               const float* __restrict__ skw) {
    int p0 = blockIdx.x * 64, bt = blockIdx.y, jj = blockIdx.z, tid = threadIdx.x;
    __shared__ __align__(16) float xs[4096];
    __shared__ __align__(16) float ws[4096];
    {
        float4* xs4 = (float4*)xs;
        float4* ws4 = (float4*)ws;
        const float4* wsrc = (const float4*)(skw + (size_t)(2 * jj) * 4096);
        for (int idx = tid; idx < 1024; idx += 256) {
            int c = idx >> 4, v = idx & 15;
            xs4[idx] = *(const float4*)(x + (size_t)(bt * 64 + c) * HW + p0 + v * 4);
            ws4[idx] = wsrc[idx];
        }
    }
    __syncthreads();
    int pi = (tid & 15) * 4, o0 = (tid >> 4) * 4;
    float4 a[4];
    #pragma unroll
    for (int k = 0; k < 4; k++) a[k] = make_float4(0.f, 0.f, 0.f, 0.f);
    #pragma unroll 4
    for (int i = 0; i < 64; i++) {
        float4 xv = *(const float4*)(xs + i * 64 + pi);
        float4 wv = *(const float4*)(ws + i * 64 + o0);
        a[0].x += wv.x*xv.x; a[0].y += wv.x*xv.y; a[0].z += wv.x*xv.z; a[0].w += wv.x*xv.w;
        a[1].x += wv.y*xv.x; a[1].y += wv.y*xv.y; a[1].z += wv.y*xv.z; a[1].w += wv.y*xv.w;
        a[2].x += wv.z*xv.x; a[2].y += wv.z*xv.y; a[2].z += wv.z*xv.z; a[2].w += wv.z*xv.w;
        a[3].x += wv.w*xv.x; a[3].y += wv.w*xv.y; a[3].z += wv.w*xv.z; a[3].w += wv.w*xv.w;
    }
    #pragma unroll
    for (int oi = 0; oi < 4; oi++)
        *(float4*)(g_Ax + ((size_t)(jj * 32 + bt) * 64 + o0 + oi) * HW + p0 + pi) = a[oi];
}

// S13[w][b][o][p] = sum_i h[b][i][p] * skw[1 or 3][i][o]
__global__ __launch_bounds__(256) void k_hskip13(const float* __restrict__ skw) {
    int p0 = blockIdx.x * 64, b = blockIdx.y, tid = threadIdx.x;
    __shared__ __align__(16) float hs[4096];
    __shared__ __align__(16) float w1s[4096];
    __shared__ __align__(16) float w3s[4096];
    {
        float4* h4 = (float4*)hs;
        float4* a4 = (float4*)w1s;
        float4* b4 = (float4*)w3s;
        const float4* w1src = (const float4*)(skw + 4096);
        const float4* w3src = (const float4*)(skw + 3 * 4096);
        for (int idx = tid; idx < 1024; idx += 256) {
            int c = idx >> 4, v = idx & 15;
            h4[idx] = *(const float4*)(g_h + (size_t)(b * 64 + c) * HW + p0 + v * 4);
            a4[idx] = w1src[idx];
            b4[idx] = w3src[idx];
        }
    }
    __syncthreads();
    int pi = (tid & 15) * 4, o0 = (tid >> 4) * 4;
    float4 a1[4], a3[4];
    #pragma unroll
    for (int k = 0; k < 4; k++) { a1[k] = make_float4(0,0,0,0); a3[k] = make_float4(0,0,0,0); }
    #pragma unroll 2
    for (int i = 0; i < 64; i++) {
        float4 xv = *(const float4*)(hs + i * 64 + pi);
        float4 wa = *(const float4*)(w1s + i * 64 + o0);
        float4 wb = *(const float4*)(w3s + i * 64 + o0);
        a1[0].x += wa.x*xv.x; a1[0].y += wa.x*xv.y; a1[0].z += wa.x*xv.z; a1[0].w += wa.x*xv.w;
        a1[1].x += wa.y*xv.x; a1[1].y += wa.y*xv.y; a1[1].z += wa.y*xv.z; a1[1].w += wa.y*xv.w;
        a1[2].x += wa.z*xv.x; a1[2].y += wa.z*xv.y; a1[2].z += wa.z*xv.z; a1[2].w += wa.z*xv.w;
        a1[3].x += wa.w*xv.x; a1[3].y += wa.w*xv.y; a1[3].z += wa.w*xv.z; a1[3].w += wa.w*xv.w;
        a3[0].x += wb.x*xv.x; a3[0].y += wb.x*xv.y; a3[0].z += wb.x*xv.z; a3[0].w += wb.x*xv.w;
        a3[1].x += wb.y*xv.x; a3[1].y += wb.y*xv.y; a3[1].z += wb.y*xv.z; a3[1].w += wb.y*xv.w;
        a3[2].x += wb.z*xv.x; a3[2].y += wb.z*xv.y; a3[2].z += wb.z*xv.z; a3[2].w += wb.z*xv.w;
        a3[3].x += wb.w*xv.x; a3[3].y += wb.w*xv.y; a3[3].z += wb.w*xv.z; a3[3].w += wb.w*xv.w;
    }
    #pragma unroll
    for (int oi = 0; oi < 4; oi++) {
        *(float4*)(g_S13 + ((size_t)(0 * 4 + b) * 64 + o0 + oi) * HW + p0 + pi) = a1[oi];
        *(float4*)(g_S13 + ((size_t)(1 * 4 + b) * 64 + o0 + oi) * HW + p0 + pi) = a3[oi];
    }
}

// S5[b][o][p] = sum_i rh[b][i][p] * skw[5][i][o]
__global__ __launch_bounds__(256) void k_skip5(const float* __restrict__ skw) {
    int p0 = blockIdx.x * 64, b = blockIdx.y, tid = threadIdx.x;
    __shared__ __align__(16) float rs[4096];
    __shared__ __align__(16) float ws[4096];
    {
        float4* r4 = (float4*)rs;
        float4* w4 = (float4*)ws;
        const float4* wsrc = (const float4*)(skw + 5 * 4096);
        for (int idx = tid; idx < 1024; idx += 256) {
            int c = idx >> 4, v = idx & 15;
            r4[idx] = *(const float4*)(g_rh + (size_t)(b * 64 + c) * HW + p0 + v * 4);
            w4[idx] = wsrc[idx];
        }
    }
    __syncthreads();
    int pi = (tid & 15) * 4, o0 = (tid >> 4) * 4;
    float4 a[4];
    #pragma unroll
    for (int k = 0; k < 4; k++) a[k] = make_float4(0.f, 0.f, 0.f, 0.f);
    #pragma unroll 4
    for (int i = 0; i < 64; i++) {
        float4 xv = *(const float4*)(rs + i * 64 + pi);
        float4 wv = *(const float4*)(ws + i * 64 + o0);
        a[0].x += wv.x*xv.x; a[0].y += wv.x*xv.y; a[0].z += wv.x*xv.z; a[0].w += wv.x*xv.w;
        a[1].x += wv.y*xv.x; a[1].y += wv.y*xv.y; a[1].z += wv.y*xv.z; a[1].w += wv.y*xv.w;
        a[2].x += wv.z*xv.x; a[2].y += wv.z*xv.y; a[2].z += wv.z*xv.z; a[2].w += wv.z*xv.w;
        a[3].x += wv.w*xv.x; a[3].y += wv.w*xv.y; a[3].z += wv.w*xv.z; a[3].w += wv.w*xv.w;
    }
    #pragma unroll
    for (int oi = 0; oi < 4; oi++)
        *(float4*)(g_S5 + ((size_t)b * 64 + o0 + oi) * HW + p0 + pi) = a[oi];
}

// inverse DFT of z/r spectra + gate epilogue + FUSED forward DFT of rh
__global__ __launch_bounds__(256) void k_invzrF(const float* __restrict__ gb, int t) {
    int img = blockIdx.x, tid = threadIdx.x;
    int b = img >> 6, o = img & 63;
    __shared__ float Zr[2][512], Zi[2][512];
    __shared__ __align__(16) float Gr[2][16 * 68];
    __shared__ __align__(16) float Gi[2][16 * 68];
    __shared__ float xs[64 * 65];
    __shared__ float cs[64], ss[64];
    if (tid < 64) { cs[tid] = g_c[tid]; ss[tid] = g_s[tid]; }
    #pragma unroll
    for (int jj = 0; jj < 2; jj++)
        for (int idx = tid; idx < 512; idx += 256) {
            float2 v = g_specF[(size_t)jj * NM * 256 + (size_t)idx * 256 + img];
            Zr[jj][idx] = v.x; Zi[jj][idx] = v.y;
        }
    __syncthreads();
    {
        int ky = tid & 15, xg = tid >> 4, x0 = xg * 4;
        #pragma unroll
        for (int jj = 0; jj < 2; jj++) {
            float gr[4] = {0,0,0,0}, gi[4] = {0,0,0,0};
            #pragma unroll 4
            for (int kxi = 0; kxi < 32; kxi++) {
                int kx = kxi + ((kxi >= 16) ? 32 : 0);
                float zr = Zr[jj][kxi * 16 + ky], zi = Zi[jj][kxi * 16 + ky];
                #pragma unroll
                for (int k = 0; k < 4; k++) {
                    int id = (kx * (x0 + k)) & 63;
                    float c = cs[id], s = ss[id];
                    gr[k] += zr * c - zi * s;
                    gi[k] += zr * s + zi * c;
                }
            }
            #pragma unroll
            for (int k = 0; k < 4; k++) { Gr[jj][ky*68 + x0+k] = gr[k]; Gi[jj][ky*68 + x0+k] = gi[k]; }
        }
    }
    __syncthreads();
    {
        int y = tid & 63, xq = tid >> 6;
        float a0[16], a1[16];
        #pragma unroll
        for (int q = 0; q < 16; q++) { a0[q] = 0.f; a1[q] = 0.f; }
        for (int ky = 0; ky < 16; ky++) {
            int id = (ky * y) & 63;
            float c = cs[id], s = ss[id];
            const float4* ar4 = (const float4*)(Gr[0] + ky * 68 + xq * 16);
            const float4* ai4 = (const float4*)(Gi[0] + ky * 68 + xq * 16);
            const float4* br4 = (const float4*)(Gr[1] + ky * 68 + xq * 16);
            const float4* bi4 = (const float4*)(Gi[1] + ky * 68 + xq * 16);
            #pragma unroll
            for (int q = 0; q < 4; q++) {
                float4 xr = ar4[q], xi = ai4[q];
                a0[q*4+0] += xr.x * c - xi.x * s;
                a0[q*4+1] += xr.y * c - xi.y * s;
                a0[q*4+2] += xr.z * c - xi.z * s;
                a0[q*4+3] += xr.w * c - xi.w * s;
                float4 yr = br4[q], yi = bi4[q];
                a1[q*4+0] += yr.x * c - yi.x * s;
                a1[q*4+1] += yr.y * c - yi.y * s;
                a1[q*4+2] += yr.z * c - yi.z * s;
                a1[q*4+3] += yr.w * c - yi.w * s;
            }
        }
        float gb0 = gb[0], gb1 = gb[1];
        int bt = b * 8 + t;
        const float* ax0 = g_Ax + ((size_t)(0 * 32 + bt) * 64 + o) * HW;
        const float* ax1 = g_Ax + ((size_t)(1 * 32 + bt) * 64 + o) * HW;
        const float* s1p = g_S13 + ((size_t)(0 * 4 + b) * 64 + o) * HW;
        const float* s3p = g_S13 + ((size_t)(1 * 4 + b) * 64 + o) * HW;
        const float* hp  = g_h + (size_t)img * HW;
        float* zp  = g_z + (size_t)img * HW;
        float* rhp = g_rh + (size_t)img * HW;
        #pragma unroll
        for (int q = 0; q < 16; q++) {
            int x = xq * 16 + q;
            int off = x * 64 + y;
            float pre0 = a0[q] + ax0[off] + s1p[off] + gb0;
            float pre1 = a1[q] + ax1[off] + s3p[off] + gb1;
            float z = 1.f / (1.f + expf(-pre0));
            float r = 1.f / (1.f + expf(-pre1));
            float rh = r * hp[off];
            zp[off]  = z;
            rhp[off] = rh;
            xs[x * 65 + y] = rh;
        }
    }
    __syncthreads();
    float* Yre = Gr[0];
    float* Yim = Gi[0];
    {
        int x = tid >> 2, kq = tid & 3;
        const float* row = xs + x * 65;
        float ar[4] = {0,0,0,0}, ai[4] = {0,0,0,0};
        int ii[4] = {0,0,0,0};
        #pragma unroll 8
        for (int y = 0; y < 64; y++) {
            float v = row[y];
            #pragma unroll
            for (int k = 0; k < 4; k++) {
                ar[k] += v * cs[ii[k]];
                ai[k] -= v * ss[ii[k]];
                ii[k] = (ii[k] + kq * 4 + k) & 63;
            }
        }
        #pragma unroll
        for (int k = 0; k < 4; k++) { Yre[x*17 + kq*4+k] = ar[k]; Yim[x*17 + kq*4+k] = ai[k]; }
    }
    __syncthreads();
    {
        int ky = tid & 15, kg = tid >> 4;
        float z0r=0, z0i=0, z1r=0, z1i=0;
        int i0 = 0, i1 = 0;
        #pragma unroll 8
        for (int x = 0; x < 64; x++) {
            float yr = Yre[x*17 + ky], yi = Yim[x*17 + ky];
            float c = cs[i0], s = ss[i0];
            z0r += yr*c + yi*s; z0i += yi*c - yr*s;
            c = cs[i1]; s = ss[i1];
            z1r += yr*c + yi*s; z1i += yi*c - yr*s;
            i0 = (i0 + kg) & 63; i1 = (i1 + kg + 48) & 63;
        }
        g_specH[(size_t)(kg * 16 + ky) * 256 + img]        = make_float2(z0r, z0i);
        g_specH[(size_t)((kg + 16) * 16 + ky) * 256 + img] = make_float2(z1r, z1i);
    }
}

// inverse DFT of h_hat + selu + blend -> new h, FUSED forward DFT of new h
__global__ __launch_bounds__(256) void k_inv5F(const float* __restrict__ gb, int t) {
    int img = blockIdx.x, tid = threadIdx.x;
    int b = img >> 6, o = img & 63;
    __shared__ float Zr[512], Zi[512];
    __shared__ __align__(16) float Gr[16 * 68];
    __shared__ __align__(16) float Gi[16 * 68];
    __shared__ float xs[64 * 65];
    __shared__ float cs[64], ss[64];
    if (tid < 64) { cs[tid] = g_c[tid]; ss[tid] = g_s[tid]; }
    for (int idx = tid; idx < 512; idx += 256) {
        float2 v = g_specF[(size_t)idx * 256 + img];
        Zr[idx] = v.x; Zi[idx] = v.y;
    }
    __syncthreads();
    {
        int ky = tid & 15, xg = tid >> 4, x0 = xg * 4;
        float gr[4] = {0,0,0,0}, gi[4] = {0,0,0,0};
        #pragma unroll 4
        for (int kxi = 0; kxi < 32; kxi++) {
            int kx = kxi + ((kxi >= 16) ? 32 : 0);
            float zr = Zr[kxi * 16 + ky], zi = Zi[kxi * 16 + ky];
            #pragma unroll
            for (int k = 0; k < 4; k++) {
                int id = (kx * (x0 + k)) & 63;
                float c = cs[id], s = ss[id];
                gr[k] += zr * c - zi * s;
                gi[k] += zr * s + zi * c;
            }
        }
        #pragma unroll
        for (int k = 0; k < 4; k++) { Gr[ky*68 + x0+k] = gr[k]; Gi[ky*68 + x0+k] = gi[k]; }
    }
    __syncthreads();
    {
        int y = tid & 63, xq = tid >> 6;
        float acc[16];
        #pragma unroll
        for (int q = 0; q < 16; q++) acc[q] = 0.f;
        for (int ky = 0; ky < 16; ky++) {
            int id = (ky * y) & 63;
            float c = cs[id], s = ss[id];
            const float4* a4 = (const float4*)(Gr + ky * 68 + xq * 16);
            const float4* b4 = (const float4*)(Gi + ky * 68 + xq * 16);
            #pragma unroll
            for (int q = 0; q < 4; q++) {
                float4 a = a4[q], bb = b4[q];
                acc[q*4+0] += a.x * c - bb.x * s;
                acc[q*4+1] += a.y * c - bb.y * s;
                acc[q*4+2] += a.z * c - bb.z * s;
                acc[q*4+3] += a.w * c - bb.w * s;
            }
        }
        float gb2 = gb[2];
        int bt = b * 8 + t;
        const float* ax2 = g_Ax + ((size_t)(2 * 32 + bt) * 64 + o) * HW;
        const float* s5p = g_S5 + ((size_t)b * 64 + o) * HW;
        const float* zp  = g_z + (size_t)img * HW;
        float* hp = g_h + (size_t)img * HW;
        const float SC = 1.0507009873554805f, AL = 1.6732632423543772f;
        #pragma unroll
        for (int q = 0; q < 16; q++) {
            int x = xq * 16 + q;
            int off = x * 64 + y;
            float v = acc[q] + ax2[off] + s5p[off] + gb2;
            float hh = (v > 0.f) ? SC * v : SC * AL * (expf(v) - 1.f);
            float z = zp[off], h = hp[off];
            float hn = (1.f - z) * h + z * hh;
            hp[off] = hn;
            xs[x * 65 + y] = hn;
        }
    }
    __syncthreads();
    float* Yre = Gr;
    float* Yim = Gi;
    {
        int x = tid >> 2, kq = tid & 3;
        const float* row = xs + x * 65;
        float ar[4] = {0,0,0,0}, ai[4] = {0,0,0,0};
        int ii[4] = {0,0,0,0};
        #pragma unroll 8
        for (int y = 0; y < 64; y++) {
            float v = row[y];
            #pragma unroll
            for (int k = 0; k < 4; k++) {
                ar[k] += v * cs[ii[k]];
                ai[k] -= v * ss[ii[k]];
                ii[k] = (ii[k] + kq * 4 + k) & 63;
            }
        }
        #pragma unroll
        for (int k = 0; k < 4; k++) { Yre[x*17 + kq*4+k] = ar[k]; Yim[x*17 + kq*4+k] = ai[k]; }
    }
    __syncthreads();
    {
        int ky = tid & 15, kg = tid >> 4;
        float z0r=0, z0i=0, z1r=0, z1i=0;
        int i0 = 0, i1 = 0;
        #pragma unroll 8
        for (int x = 0; x < 64; x++) {
            float yr = Yre[x*17 + ky], yi = Yim[x*17 + ky];
            float c = cs[i0], s = ss[i0];
            z0r += yr*c + yi*s; z0i += yi*c - yr*s;
            c = cs[i1]; s = ss[i1];
            z1r += yr*c + yi*s; z1i += yi*c - yr*s;
            i0 = (i0 + kg) & 63; i1 = (i1 + kg + 48) & 63;
        }
        g_specH[(size_t)(kg * 16 + ky) * 256 + img]        = make_float2(z0r, z0i);
        g_specH[(size_t)((kg + 16) * 16 + ky) * 256 + img] = make_float2(z1r, z1i);
    }
}

__global__ void k_copy(float* __restrict__ out) {
    int idx = blockIdx.x * 256 + threadIdx.x;
    out[idx] = g_h[idx];
}

extern "C" void kernel_launch(void* const* d_in, const int* in_sizes, int n_in,
                              void* d_out, int out_size) {
    const float* x   = (const float*)d_in[0];
    const float* sw1 = (const float*)d_in[1];
    const float* sw2 = (const float*)d_in[2];
    const float* skw = (const float*)d_in[3];
    const float* gb  = (const float*)d_in[4];
    const float* bh  = (const float*)d_in[5];
    float* out = (float*)d_out;

    float2 *pSpecX, *pSpecH, *pSpecF;
    float *pH;
    cudaGetSymbolAddress((void**)&pSpecX, g_specX);
    cudaGetSymbolAddress((void**)&pSpecH, g_specH);
    cudaGetSymbolAddress((void**)&pSpecF, g_specF);
    cudaGetSymbolAddress((void**)&pH, g_h);

    static cudaStream_t s1 = nullptr, s2 = nullptr;
    static cudaEvent_t e0, e1, e2;
    static cudaEvent_t eA[8], eB[8], eC[8], eD[8];
    if (!s1) {
        cudaStreamCreateWithFlags(&s1, cudaStreamNonBlocking);
        cudaStreamCreateWithFlags(&s2, cudaStreamNonBlocking);
        cudaEventCreateWithFlags(&e0, cudaEventDisableTiming);
        cudaEventCreateWithFlags(&e1, cudaEventDisableTiming);
        cudaEventCreateWithFlags(&e2, cudaEventDisableTiming);
        for (int t = 0; t < 8; t++) {
            cudaEventCreateWithFlags(&eA[t], cudaEventDisableTiming);
            cudaEventCreateWithFlags(&eB[t], cudaEventDisableTiming);
            cudaEventCreateWithFlags(&eC[t], cudaEventDisableTiming);
            cudaEventCreateWithFlags(&eD[t], cudaEventDisableTiming);
        }
    }

    k_twiddle<<<1, 64>>>();
    cudaEventRecord(e0, 0);
    cudaStreamWaitEvent(s1, e0, 0);
    cudaStreamWaitEvent(s2, e0, 0);

    // default stream: weight transpose (bandwidth-bound, overlaps with s1/s2)
    k_wtrans<<<3072, 256>>>(sw1, sw2);

    // s1: x-dependent precompute
    k_skipx<<<dim3(64, 32, 3), 256, 0, s1>>>(x, skw);
    k_fwd<<<2048, 256, 0, s1>>>(x, pSpecX, 2048);
    cudaEventRecord(e1, s1);

    // s2: h0 branch
    k_hinit<<<4096, 256, 0, s2>>>(bh);
    k_fwd<<<256, 256, 0, s2>>>(pH, pSpecH, 256);
    k_hskip13<<<dim3(64, 4), 256, 0, s2>>>(skw);
    cudaEventRecord(e2, s2);

    // join: mix32 needs wtrans (default) + specX (e1); invPre needs mix32 + Ax (e1)
    cudaStreamWaitEvent(0, e1, 0);
    k_mix32<<<dim3(512, 3), 256>>>();
    k_invPre<<<dim3(2048, 3), 256>>>();
    cudaStreamWaitEvent(0, e2, 0);

    // Recurrent loop with parallel forks:
    //  default: mix13 -> invzrF -> mix5 -> (wait S5) -> inv5F -> mix13(t+1) ...
    //  s1:                skip5 (after invzrF) ;  hskip13 (after inv5F)
    for (int t = 0; t < 8; t++) {
        k_mix4<<<dim3(512, 2), 256>>>(pSpecH, pSpecF, 1, 3);
        k_invzrF<<<256, 256>>>(gb, t);              // z, rh, specH(rh)
        cudaEventRecord(eA[t], 0);
        cudaStreamWaitEvent(s1, eA[t], 0);
        k_skip5<<<dim3(64, 4), 256, 0, s1>>>(skw);  // S5 (parallel with mix5)
        cudaEventRecord(eB[t], s1);
        k_mix4<<<dim3(512, 1), 256>>>(pSpecH, pSpecF, 5, 5);
        cudaStreamWaitEvent(0, eB[t], 0);
        k_inv5F<<<256, 256>>>(gb, t);               // new h, specH(h')
        if (t < 7) {
            cudaEventRecord(eC[t], 0);
            cudaStreamWaitEvent(s1, eC[t], 0);
            k_hskip13<<<dim3(64, 4), 256, 0, s1>>>(skw);  // parallel with mix13(t+1)
            cudaEventRecord(eD[t], s1);
            cudaStreamWaitEvent(0, eD[t], 0);
        }
    }
    k_copy<<<4096, 256>>>(out);
}